// round 10
// baseline (speedup 1.0000x reference)
#include <cuda_runtime.h>
#include <cuda_bf16.h>
#include <cuda_fp16.h>
#include <cstdint>

#define Bn 8
#define SQn 2048
#define SKn 2048
#define Dh 512
#define NKT 16
#define NQT 16
#define THREADS 512
#define PITCHB 144                 // bytes per smem tile row (64 elems*2B + 16B pad)
#define TB2 (128 * PITCHB)         // 18432 bytes per tile
#define BUFB (4 * TB2)             // 73728 per buffer
#define NSTAGE 3
#define TILES_OFF 2048
#define SMEM_BYTES (TILES_OFF + NSTAGE * BUFB)

__device__ __nv_bfloat16 g_Qh[Bn * SQn * Dh], g_Ql[Bn * SQn * Dh];
__device__ __nv_bfloat16 g_Kh[Bn * SKn * Dh], g_Kl[Bn * SKn * Dh];
__device__ __half g_Vf[(size_t)Bn * SKn * Dh];     // fp16, transposed [b][d][sk]
__device__ float g_S[(size_t)Bn * SQn * SKn];
__device__ __half g_Pf[(size_t)Bn * SQn * SKn];    // fp16 P

// ---------------- helpers ----------------
__device__ __forceinline__ uint32_t smem_to_u32(const void* p) {
    uint32_t a;
    asm("{ .reg .u64 t; cvta.to.shared.u64 t, %1; cvt.u32.u64 %0, t; }" : "=r"(a) : "l"(p));
    return a;
}
__device__ __forceinline__ void ldsm4(uint32_t* r, uint32_t addr) {
    asm volatile("ldmatrix.sync.aligned.m8n8.x4.shared.b16 {%0,%1,%2,%3}, [%4];"
        : "=r"(r[0]), "=r"(r[1]), "=r"(r[2]), "=r"(r[3]) : "r"(addr));
}
__device__ __forceinline__ void mma16816(float* c, const uint32_t* a, const uint32_t* b) {
    asm volatile("mma.sync.aligned.m16n8k16.row.col.f32.bf16.bf16.f32 "
        "{%0,%1,%2,%3}, {%4,%5,%6,%7}, {%8,%9}, {%0,%1,%2,%3};"
        : "+f"(c[0]), "+f"(c[1]), "+f"(c[2]), "+f"(c[3])
        : "r"(a[0]), "r"(a[1]), "r"(a[2]), "r"(a[3]), "r"(b[0]), "r"(b[1]));
}
__device__ __forceinline__ void mma16816h(float* c, const uint32_t* a, const uint32_t* b) {
    asm volatile("mma.sync.aligned.m16n8k16.row.col.f32.f16.f16.f32 "
        "{%0,%1,%2,%3}, {%4,%5,%6,%7}, {%8,%9}, {%0,%1,%2,%3};"
        : "+f"(c[0]), "+f"(c[1]), "+f"(c[2]), "+f"(c[3])
        : "r"(a[0]), "r"(a[1]), "r"(a[2]), "r"(a[3]), "r"(b[0]), "r"(b[1]));
}
__device__ __forceinline__ void cpasync16(uint32_t dst, const void* src) {
    asm volatile("cp.async.cg.shared.global [%0], [%1], 16;" :: "r"(dst), "l"(src));
}
#define CP_COMMIT() asm volatile("cp.async.commit_group;" ::: "memory")
#define CP_WAIT1()  asm volatile("cp.async.wait_group 1;" ::: "memory")
__device__ __forceinline__ unsigned short uh(__half h) { return __half_as_ushort(h); }

// ---------------- prep (single kernel: QK split + V transpose->fp16) ----------------
__global__ void prep_all(const float* __restrict__ q, const float* __restrict__ k,
                         const float* __restrict__ v) {
    __shared__ float t[32][33];
    const int b = blockIdx.z;
    const int sk0 = blockIdx.x * 32, d0 = blockIdx.y * 32;
    const int tx = threadIdx.x & 31, ty = threadIdx.x >> 5;
    #pragma unroll
    for (int rr = 0; rr < 32; rr += 8)
        t[ty + rr][tx] = v[(((size_t)b * SKn + sk0 + ty + rr) << 9) + d0 + tx];
    __syncthreads();
    #pragma unroll
    for (int rr = 0; rr < 32; rr += 8) {
        int d = d0 + ty + rr;
        g_Vf[((size_t)b * Dh + d) * SKn + sk0 + tx] = __float2half(t[tx][ty + rr]);
    }
    const int n = Bn * SQn * Dh;
    const int gid = (blockIdx.z * gridDim.y * gridDim.x + blockIdx.y * gridDim.x + blockIdx.x)
                    * blockDim.x + threadIdx.x;
    const int stride = gridDim.x * gridDim.y * gridDim.z * blockDim.x;
    for (int i = gid; i < n; i += stride) {
        float x = q[i];
        __nv_bfloat16 h = __float2bfloat16(x);
        g_Qh[i] = h;
        g_Ql[i] = __float2bfloat16(x - __bfloat162float(h));
        float y = k[i];
        __nv_bfloat16 g = __float2bfloat16(y);
        g_Kh[i] = g;
        g_Kl[i] = __float2bfloat16(y - __bfloat162float(g));
    }
}

__global__ void __launch_bounds__(THREADS, 1)
attn_main(float* __restrict__ out) {
    extern __shared__ char smem[];
    float* rowmax2 = (float*)smem;              // [2][128]
    float* rowsum = (float*)(smem + 1024);      // [128]
    const uint32_t sTiles = smem_to_u32(smem) + TILES_OFF;

    const int tid = threadIdx.x, wid = tid >> 5, lane = tid & 31;
    const int wq = wid >> 1, nh = wid & 1;
    const int qt = blockIdx.x, b = blockIdx.y;

    const __nv_bfloat16* Qh = g_Qh + ((size_t)b * SQn + qt * 128) * Dh;
    const __nv_bfloat16* Ql = g_Ql + ((size_t)b * SQn + qt * 128) * Dh;
    const __nv_bfloat16* Kh = g_Kh + (size_t)b * SKn * Dh;
    const __nv_bfloat16* Kl = g_Kl + (size_t)b * SKn * Dh;
    const __half* Vf = g_Vf + (size_t)b * Dh * SKn;
    float* strip = g_S + ((size_t)(b * NQT + qt)) * ((size_t)128 * SKn);
    __half* Pf = g_Pf + ((size_t)b * SQn + qt * 128) * SKn;

    if (tid < 256) rowmax2[tid] = -1e30f;

    const uint32_t aoff = (uint32_t)((wq * 16 + (lane & 7) + ((lane >> 3) & 1) * 8) * PITCHB
                                     + (lane >> 4) * 16);
    const uint32_t boff = (uint32_t)((nh * 64 + (lane & 7) + (lane >> 4) * 8) * PITCHB
                                     + ((lane >> 3) & 1) * 16);
    const int fr0 = tid >> 2, fc0 = (tid & 3) << 1;

    float acc[8][4];

    // ================= PHASE 1: S = Q K^T (bf16x3), 3-stage pipeline =================
    {
        #pragma unroll
        for (int s = 0; s < 2; s++) {
            uint32_t base = sTiles + s * BUFB;
            int kt1 = s >> 3, dc1 = s & 7;
            #pragma unroll
            for (int j = 0; j < 2; j++) {
                int r = fr0, c = fc0 + j;
                uint32_t d = base + (uint32_t)(r * PITCHB + c * 16);
                size_t qo = (size_t)r * Dh + dc1 * 64 + c * 8;
                size_t ko = (size_t)(kt1 * 128 + r) * Dh + dc1 * 64 + c * 8;
                cpasync16(d, Qh + qo);
                cpasync16(d + TB2, Ql + qo);
                cpasync16(d + 2 * TB2, Kh + ko);
                cpasync16(d + 3 * TB2, Kl + ko);
            }
            CP_COMMIT();
        }
        for (int step = 0; step < 128; step++) {
            const int dc = step & 7;
            if (dc == 0) {
                #pragma unroll
                for (int f = 0; f < 8; f++)
                    #pragma unroll
                    for (int j = 0; j < 4; j++) acc[f][j] = 0.0f;
            }
            CP_WAIT1();
            __syncthreads();
            if (step + 2 < 128) {
                int s2 = step + 2;
                int kt1 = s2 >> 3, dc1 = s2 & 7;
                uint32_t base = sTiles + (s2 % NSTAGE) * BUFB;
                #pragma unroll
                for (int j = 0; j < 2; j++) {
                    int r = fr0, c = fc0 + j;
                    uint32_t d = base + (uint32_t)(r * PITCHB + c * 16);
                    size_t qo = (size_t)r * Dh + dc1 * 64 + c * 8;
                    size_t ko = (size_t)(kt1 * 128 + r) * Dh + dc1 * 64 + c * 8;
                    cpasync16(d, Qh + qo);
                    cpasync16(d + TB2, Ql + qo);
                    cpasync16(d + 2 * TB2, Kh + ko);
                    cpasync16(d + 3 * TB2, Kl + ko);
                }
            }
            CP_COMMIT();
            const uint32_t sAH = sTiles + (step % NSTAGE) * BUFB;
            const uint32_t sAL = sAH + TB2, sBH = sAH + 2 * TB2, sBL = sAH + 3 * TB2;
            #pragma unroll
            for (int ks = 0; ks < 4; ks++) {
                uint32_t ah[4], al[4], bh[4][4], bl[4][4];
                ldsm4(ah, sAH + aoff + ks * 32);
                ldsm4(al, sAL + aoff + ks * 32);
                #pragma unroll
                for (int f = 0; f < 4; f++) {
                    uint32_t bo = boff + (uint32_t)(f * (16 * PITCHB) + ks * 32);
                    ldsm4(bh[f], sBH + bo);
                    ldsm4(bl[f], sBL + bo);
                }
                // pass-major: same-acc MMAs spaced 8 issues apart
                #pragma unroll
                for (int f = 0; f < 4; f++) {
                    mma16816(acc[2 * f],     ah, bh[f]);
                    mma16816(acc[2 * f + 1], ah, bh[f] + 2);
                }
                #pragma unroll
                for (int f = 0; f < 4; f++) {
                    mma16816(acc[2 * f],     ah, bl[f]);
                    mma16816(acc[2 * f + 1], ah, bl[f] + 2);
                }
                #pragma unroll
                for (int f = 0; f < 4; f++) {
                    mma16816(acc[2 * f],     al, bh[f]);
                    mma16816(acc[2 * f + 1], al, bh[f] + 2);
                }
            }
            if (dc == 7) {   // spill S tile
                const int kt = step >> 3;
                int row = wq * 16 + (lane >> 2);
                int cb = nh * 64 + (lane & 3) * 2;
                float* s0 = strip + (size_t)kt * 16384 + row * 128 + cb;
                float m0 = -1e30f, m1 = -1e30f;
                #pragma unroll
                for (int f = 0; f < 8; f++) {
                    m0 = fmaxf(m0, fmaxf(acc[f][0], acc[f][1]));
                    m1 = fmaxf(m1, fmaxf(acc[f][2], acc[f][3]));
                    *(float2*)(s0 + f * 8) = make_float2(acc[f][0], acc[f][1]);
                    *(float2*)(s0 + 8 * 128 + f * 8) = make_float2(acc[f][2], acc[f][3]);
                }
                m0 = fmaxf(m0, __shfl_xor_sync(0xffffffffu, m0, 1));
                m0 = fmaxf(m0, __shfl_xor_sync(0xffffffffu, m0, 2));
                m1 = fmaxf(m1, __shfl_xor_sync(0xffffffffu, m1, 1));
                m1 = fmaxf(m1, __shfl_xor_sync(0xffffffffu, m1, 2));
                if ((lane & 3) == 0) {
                    float* rm = rowmax2 + nh * 128;
                    rm[row] = fmaxf(rm[row], m0);
                    rm[row + 8] = fmaxf(rm[row + 8], m1);
                }
            }
        }
    }
    __syncthreads();

    // ================= PHASE 2: softmax -> fp16 P =================
    for (int i = 0; i < 8; i++) {
        int r = wid * 8 + i;
        float m = fmaxf(rowmax2[r], rowmax2[128 + r]);
        float s = 0.0f;
        for (int kt = 0; kt < NKT; kt++) {
            float4 vv = *(const float4*)(strip + (size_t)kt * 16384 + r * 128 + lane * 4);
            float p0 = __expf(vv.x - m), p1 = __expf(vv.y - m);
            float p2 = __expf(vv.z - m), p3 = __expf(vv.w - m);
            s += (p0 + p1) + (p2 + p3);
            uint2 hw;
            hw.x = (uint32_t)uh(__float2half(p0)) | ((uint32_t)uh(__float2half(p1)) << 16);
            hw.y = (uint32_t)uh(__float2half(p2)) | ((uint32_t)uh(__float2half(p3)) << 16);
            *(uint2*)(Pf + (size_t)r * SKn + kt * 128 + lane * 4) = hw;
        }
        #pragma unroll
        for (int off = 16; off; off >>= 1) s += __shfl_xor_sync(0xffffffffu, s, off);
        if (lane == 0) rowsum[r] = s;
    }
    __syncthreads();

    // ================= PHASE 3: O = P V (fp16 single pass), 3-stage pipeline =================
    {
        #pragma unroll
        for (int s = 0; s < 2; s++) {
            uint32_t base = sTiles + s * BUFB;
            int dc1 = s >> 5, t1 = s & 31;
            #pragma unroll
            for (int j = 0; j < 2; j++) {
                int r = fr0, c = fc0 + j;
                uint32_t d = base + (uint32_t)(r * PITCHB + c * 16);
                cpasync16(d, Pf + (size_t)r * SKn + t1 * 64 + c * 8);
                cpasync16(d + TB2, Vf + (size_t)(dc1 * 128 + r) * SKn + t1 * 64 + c * 8);
            }
            CP_COMMIT();
        }
        for (int step = 0; step < 128; step++) {
            const int dc = step >> 5, t = step & 31;
            if (t == 0) {
                #pragma unroll
                for (int f = 0; f < 8; f++)
                    #pragma unroll
                    for (int j = 0; j < 4; j++) acc[f][j] = 0.0f;
            }
            CP_WAIT1();
            __syncthreads();
            if (step + 2 < 128) {
                int s2 = step + 2;
                int dc1 = s2 >> 5, t1 = s2 & 31;
                uint32_t base = sTiles + (s2 % NSTAGE) * BUFB;
                #pragma unroll
                for (int j = 0; j < 2; j++) {
                    int r = fr0, c = fc0 + j;
                    uint32_t d = base + (uint32_t)(r * PITCHB + c * 16);
                    cpasync16(d, Pf + (size_t)r * SKn + t1 * 64 + c * 8);
                    cpasync16(d + TB2, Vf + (size_t)(dc1 * 128 + r) * SKn + t1 * 64 + c * 8);
                }
            }
            CP_COMMIT();
            const uint32_t sA = sTiles + (step % NSTAGE) * BUFB;
            const uint32_t sB = sA + TB2;
            #pragma unroll
            for (int ks = 0; ks < 4; ks++) {
                uint32_t a4[4], b4[4][4];
                ldsm4(a4, sA + aoff + ks * 32);
                #pragma unroll
                for (int f = 0; f < 4; f++)
                    ldsm4(b4[f], sB + boff + (uint32_t)(f * (16 * PITCHB) + ks * 32));
                #pragma unroll
                for (int f = 0; f < 4; f++) {
                    mma16816h(acc[2 * f],     a4, b4[f]);
                    mma16816h(acc[2 * f + 1], a4, b4[f] + 2);
                }
            }
            if (t == 31) {
                int row = wq * 16 + (lane >> 2);
                float inv0 = 1.0f / rowsum[row];
                float inv1 = 1.0f / rowsum[row + 8];
                float* o0 = out + ((size_t)b * SQn + qt * 128 + row) * Dh + dc * 128 + nh * 64 + (lane & 3) * 2;
                float* o1 = o0 + 8 * Dh;
                #pragma unroll
                for (int f = 0; f < 8; f++) {
                    *(float2*)(o0 + f * 8) = make_float2(acc[f][0] * inv0, acc[f][1] * inv0);
                    *(float2*)(o1 + f * 8) = make_float2(acc[f][2] * inv1, acc[f][3] * inv1);
                }
            }
        }
    }
}

extern "C" void kernel_launch(void* const* d_in, const int* in_sizes, int n_in,
                              void* d_out, int out_size) {
    (void)in_sizes; (void)n_in; (void)out_size;
    const float* q = (const float*)d_in[0];
    const float* k = (const float*)d_in[1];
    const float* v = (const float*)d_in[2];
    float* out = (float*)d_out;

    cudaFuncSetAttribute(attn_main, cudaFuncAttributeMaxDynamicSharedMemorySize, SMEM_BYTES);

    dim3 pgrid(SKn / 32, Dh / 32, Bn);
    prep_all<<<pgrid, 256>>>(q, k, v);
    dim3 grid(NQT, Bn);
    attn_main<<<grid, THREADS, SMEM_BYTES>>>(out);
}

// round 11
// speedup vs baseline: 1.0323x; 1.0323x over previous
#include <cuda_runtime.h>
#include <cuda_bf16.h>
#include <cuda_fp16.h>
#include <cstdint>

#define Bn 8
#define SQn 2048
#define SKn 2048
#define Dh 512
#define NKT 16
#define NQT 16
#define THREADS 1024
#define PITCHB 144                 // bytes per smem tile row (64 elems*2B + 16B pad)
#define TB2 (128 * PITCHB)         // 18432 bytes per tile
#define BUFB (4 * TB2)             // 73728 per buffer
#define NSTAGE 3
#define TILES_OFF 4096
#define SMEM_BYTES (TILES_OFF + NSTAGE * BUFB)   // 225280

__device__ __nv_bfloat16 g_Qh[Bn * SQn * Dh], g_Ql[Bn * SQn * Dh];
__device__ __nv_bfloat16 g_Kh[Bn * SKn * Dh], g_Kl[Bn * SKn * Dh];
__device__ __half g_Vf[(size_t)Bn * SKn * Dh];     // fp16, transposed [b][d][sk]
__device__ float g_S[(size_t)Bn * SQn * SKn];
__device__ __half g_Pf[(size_t)Bn * SQn * SKn];    // fp16 P

// ---------------- helpers ----------------
__device__ __forceinline__ uint32_t smem_to_u32(const void* p) {
    uint32_t a;
    asm("{ .reg .u64 t; cvta.to.shared.u64 t, %1; cvt.u32.u64 %0, t; }" : "=r"(a) : "l"(p));
    return a;
}
__device__ __forceinline__ void ldsm4(uint32_t* r, uint32_t addr) {
    asm volatile("ldmatrix.sync.aligned.m8n8.x4.shared.b16 {%0,%1,%2,%3}, [%4];"
        : "=r"(r[0]), "=r"(r[1]), "=r"(r[2]), "=r"(r[3]) : "r"(addr));
}
__device__ __forceinline__ void mma16816(float* c, const uint32_t* a, const uint32_t* b) {
    asm volatile("mma.sync.aligned.m16n8k16.row.col.f32.bf16.bf16.f32 "
        "{%0,%1,%2,%3}, {%4,%5,%6,%7}, {%8,%9}, {%0,%1,%2,%3};"
        : "+f"(c[0]), "+f"(c[1]), "+f"(c[2]), "+f"(c[3])
        : "r"(a[0]), "r"(a[1]), "r"(a[2]), "r"(a[3]), "r"(b[0]), "r"(b[1]));
}
__device__ __forceinline__ void mma16816h(float* c, const uint32_t* a, const uint32_t* b) {
    asm volatile("mma.sync.aligned.m16n8k16.row.col.f32.f16.f16.f32 "
        "{%0,%1,%2,%3}, {%4,%5,%6,%7}, {%8,%9}, {%0,%1,%2,%3};"
        : "+f"(c[0]), "+f"(c[1]), "+f"(c[2]), "+f"(c[3])
        : "r"(a[0]), "r"(a[1]), "r"(a[2]), "r"(a[3]), "r"(b[0]), "r"(b[1]));
}
__device__ __forceinline__ void cpasync16(uint32_t dst, const void* src) {
    asm volatile("cp.async.cg.shared.global [%0], [%1], 16;" :: "r"(dst), "l"(src));
}
#define CP_COMMIT() asm volatile("cp.async.commit_group;" ::: "memory")
#define CP_WAIT1()  asm volatile("cp.async.wait_group 1;" ::: "memory")
__device__ __forceinline__ unsigned short uh(__half h) { return __half_as_ushort(h); }

// ---------------- prep ----------------
__global__ void prep_all(const float* __restrict__ q, const float* __restrict__ k,
                         const float* __restrict__ v) {
    __shared__ float t[32][33];
    const int b = blockIdx.z;
    const int sk0 = blockIdx.x * 32, d0 = blockIdx.y * 32;
    const int tx = threadIdx.x & 31, ty = threadIdx.x >> 5;
    #pragma unroll
    for (int rr = 0; rr < 32; rr += 8)
        t[ty + rr][tx] = v[(((size_t)b * SKn + sk0 + ty + rr) << 9) + d0 + tx];
    __syncthreads();
    #pragma unroll
    for (int rr = 0; rr < 32; rr += 8) {
        int d = d0 + ty + rr;
        g_Vf[((size_t)b * Dh + d) * SKn + sk0 + tx] = __float2half(t[tx][ty + rr]);
    }
    const int n = Bn * SQn * Dh;
    const int gid = (blockIdx.z * gridDim.y * gridDim.x + blockIdx.y * gridDim.x + blockIdx.x)
                    * blockDim.x + threadIdx.x;
    const int stride = gridDim.x * gridDim.y * gridDim.z * blockDim.x;
    for (int i = gid; i < n; i += stride) {
        float x = q[i];
        __nv_bfloat16 h = __float2bfloat16(x);
        g_Qh[i] = h;
        g_Ql[i] = __float2bfloat16(x - __bfloat162float(h));
        float y = k[i];
        __nv_bfloat16 g = __float2bfloat16(y);
        g_Kh[i] = g;
        g_Kl[i] = __float2bfloat16(y - __bfloat162float(g));
    }
}

__global__ void __launch_bounds__(THREADS, 1)
attn_main(float* __restrict__ out) {
    extern __shared__ char smem[];
    float* rowmax4 = (float*)smem;              // [4][128]
    float* rowsum = (float*)(smem + 2048);      // [128]
    const uint32_t sTiles = smem_to_u32(smem) + TILES_OFF;

    const int tid = threadIdx.x, wid = tid >> 5, lane = tid & 31;
    const int wq = wid >> 2, nh = wid & 3;      // 8 q-groups x 4 n-groups
    const int qt = blockIdx.x, b = blockIdx.y;

    const __nv_bfloat16* Qh = g_Qh + ((size_t)b * SQn + qt * 128) * Dh;
    const __nv_bfloat16* Ql = g_Ql + ((size_t)b * SQn + qt * 128) * Dh;
    const __nv_bfloat16* Kh = g_Kh + (size_t)b * SKn * Dh;
    const __nv_bfloat16* Kl = g_Kl + (size_t)b * SKn * Dh;
    const __half* Vf = g_Vf + (size_t)b * Dh * SKn;
    float* strip = g_S + ((size_t)(b * NQT + qt)) * ((size_t)128 * SKn);
    __half* Pf = g_Pf + ((size_t)b * SQn + qt * 128) * SKn;

    if (tid < 512) rowmax4[tid] = -1e30f;

    // A: 16 q-rows per warp; B: 32 n-cols per warp (2 n16 groups)
    const uint32_t aoff = (uint32_t)((wq * 16 + (lane & 7) + ((lane >> 3) & 1) * 8) * PITCHB
                                     + (lane >> 4) * 16);
    const uint32_t boff = (uint32_t)((nh * 32 + (lane & 7) + (lane >> 4) * 8) * PITCHB
                                     + ((lane >> 3) & 1) * 16);
    const int fr0 = tid >> 3, fc0 = tid & 7;   // fill: 1 chunk per tile per thread

    float acc[4][4];

    // ================= PHASE 1: S = Q K^T (bf16x3), 3-stage pipeline =================
    {
        #pragma unroll
        for (int s = 0; s < 2; s++) {
            uint32_t base = sTiles + s * BUFB;
            int kt1 = s >> 3, dc1 = s & 7;
            uint32_t d = base + (uint32_t)(fr0 * PITCHB + fc0 * 16);
            size_t qo = (size_t)fr0 * Dh + dc1 * 64 + fc0 * 8;
            size_t ko = (size_t)(kt1 * 128 + fr0) * Dh + dc1 * 64 + fc0 * 8;
            cpasync16(d, Qh + qo);
            cpasync16(d + TB2, Ql + qo);
            cpasync16(d + 2 * TB2, Kh + ko);
            cpasync16(d + 3 * TB2, Kl + ko);
            CP_COMMIT();
        }
        for (int step = 0; step < 128; step++) {
            const int dc = step & 7;
            if (dc == 0) {
                #pragma unroll
                for (int f = 0; f < 4; f++)
                    #pragma unroll
                    for (int j = 0; j < 4; j++) acc[f][j] = 0.0f;
            }
            CP_WAIT1();
            __syncthreads();
            if (step + 2 < 128) {
                int s2 = step + 2;
                int kt1 = s2 >> 3, dc1 = s2 & 7;
                uint32_t base = sTiles + (s2 % NSTAGE) * BUFB;
                uint32_t d = base + (uint32_t)(fr0 * PITCHB + fc0 * 16);
                size_t qo = (size_t)fr0 * Dh + dc1 * 64 + fc0 * 8;
                size_t ko = (size_t)(kt1 * 128 + fr0) * Dh + dc1 * 64 + fc0 * 8;
                cpasync16(d, Qh + qo);
                cpasync16(d + TB2, Ql + qo);
                cpasync16(d + 2 * TB2, Kh + ko);
                cpasync16(d + 3 * TB2, Kl + ko);
            }
            CP_COMMIT();
            const uint32_t sAH = sTiles + (step % NSTAGE) * BUFB;
            const uint32_t sAL = sAH + TB2, sBH = sAH + 2 * TB2, sBL = sAH + 3 * TB2;
            #pragma unroll
            for (int ks = 0; ks < 4; ks++) {
                uint32_t ah[4], al[4], bh[2][4], bl[2][4];
                ldsm4(ah, sAH + aoff + ks * 32);
                ldsm4(al, sAL + aoff + ks * 32);
                #pragma unroll
                for (int nf = 0; nf < 2; nf++) {
                    uint32_t bo = boff + (uint32_t)(nf * (16 * PITCHB) + ks * 32);
                    ldsm4(bh[nf], sBH + bo);
                    ldsm4(bl[nf], sBL + bo);
                }
                #pragma unroll
                for (int nf = 0; nf < 2; nf++)
                    #pragma unroll
                    for (int n8 = 0; n8 < 2; n8++)
                        mma16816(acc[nf * 2 + n8], ah, bh[nf] + n8 * 2);
                #pragma unroll
                for (int nf = 0; nf < 2; nf++)
                    #pragma unroll
                    for (int n8 = 0; n8 < 2; n8++)
                        mma16816(acc[nf * 2 + n8], ah, bl[nf] + n8 * 2);
                #pragma unroll
                for (int nf = 0; nf < 2; nf++)
                    #pragma unroll
                    for (int n8 = 0; n8 < 2; n8++)
                        mma16816(acc[nf * 2 + n8], al, bh[nf] + n8 * 2);
            }
            if (dc == 7) {   // spill S tile: fragments -> strip
                const int kt = step >> 3;
                int row = wq * 16 + (lane >> 2);
                float m0 = -1e30f, m1 = -1e30f;
                #pragma unroll
                for (int f = 0; f < 4; f++) {
                    int col = nh * 32 + f * 8 + (lane & 3) * 2;
                    float* s0 = strip + (size_t)kt * 16384 + row * 128 + col;
                    m0 = fmaxf(m0, fmaxf(acc[f][0], acc[f][1]));
                    m1 = fmaxf(m1, fmaxf(acc[f][2], acc[f][3]));
                    *(float2*)s0 = make_float2(acc[f][0], acc[f][1]);
                    *(float2*)(s0 + 8 * 128) = make_float2(acc[f][2], acc[f][3]);
                }
                m0 = fmaxf(m0, __shfl_xor_sync(0xffffffffu, m0, 1));
                m0 = fmaxf(m0, __shfl_xor_sync(0xffffffffu, m0, 2));
                m1 = fmaxf(m1, __shfl_xor_sync(0xffffffffu, m1, 1));
                m1 = fmaxf(m1, __shfl_xor_sync(0xffffffffu, m1, 2));
                if ((lane & 3) == 0) {
                    float* rm = rowmax4 + nh * 128;
                    rm[row] = fmaxf(rm[row], m0);
                    rm[row + 8] = fmaxf(rm[row + 8], m1);
                }
            }
        }
    }
    __syncthreads();

    // ================= PHASE 2: softmax -> fp16 P =================
    #pragma unroll
    for (int i = 0; i < 4; i++) {
        int r = wid * 4 + i;
        float m = fmaxf(fmaxf(rowmax4[r], rowmax4[128 + r]),
                        fmaxf(rowmax4[256 + r], rowmax4[384 + r]));
        float s = 0.0f;
        for (int kt = 0; kt < NKT; kt++) {
            float4 vv = *(const float4*)(strip + (size_t)kt * 16384 + r * 128 + lane * 4);
            float p0 = __expf(vv.x - m), p1 = __expf(vv.y - m);
            float p2 = __expf(vv.z - m), p3 = __expf(vv.w - m);
            s += (p0 + p1) + (p2 + p3);
            uint2 hw;
            hw.x = (uint32_t)uh(__float2half(p0)) | ((uint32_t)uh(__float2half(p1)) << 16);
            hw.y = (uint32_t)uh(__float2half(p2)) | ((uint32_t)uh(__float2half(p3)) << 16);
            *(uint2*)(Pf + (size_t)r * SKn + kt * 128 + lane * 4) = hw;
        }
        #pragma unroll
        for (int off = 16; off; off >>= 1) s += __shfl_xor_sync(0xffffffffu, s, off);
        if (lane == 0) rowsum[r] = s;
    }
    __syncthreads();

    // ================= PHASE 3: O = P V (fp16 single pass), 3-stage pipeline =================
    {
        #pragma unroll
        for (int s = 0; s < 2; s++) {
            uint32_t base = sTiles + s * BUFB;
            int dc1 = s >> 5, t1 = s & 31;
            uint32_t d = base + (uint32_t)(fr0 * PITCHB + fc0 * 16);
            cpasync16(d, Pf + (size_t)fr0 * SKn + t1 * 64 + fc0 * 8);
            cpasync16(d + TB2, Vf + (size_t)(dc1 * 128 + fr0) * SKn + t1 * 64 + fc0 * 8);
            CP_COMMIT();
        }
        for (int step = 0; step < 128; step++) {
            const int dc = step >> 5, t = step & 31;
            if (t == 0) {
                #pragma unroll
                for (int f = 0; f < 4; f++)
                    #pragma unroll
                    for (int j = 0; j < 4; j++) acc[f][j] = 0.0f;
            }
            CP_WAIT1();
            __syncthreads();
            if (step + 2 < 128) {
                int s2 = step + 2;
                int dc1 = s2 >> 5, t1 = s2 & 31;
                uint32_t base = sTiles + (s2 % NSTAGE) * BUFB;
                uint32_t d = base + (uint32_t)(fr0 * PITCHB + fc0 * 16);
                cpasync16(d, Pf + (size_t)fr0 * SKn + t1 * 64 + fc0 * 8);
                cpasync16(d + TB2, Vf + (size_t)(dc1 * 128 + fr0) * SKn + t1 * 64 + fc0 * 8);
            }
            CP_COMMIT();
            const uint32_t sA = sTiles + (step % NSTAGE) * BUFB;
            const uint32_t sB = sA + TB2;
            #pragma unroll
            for (int ks = 0; ks < 4; ks++) {
                uint32_t a4[4], b4[2][4];
                ldsm4(a4, sA + aoff + ks * 32);
                #pragma unroll
                for (int nf = 0; nf < 2; nf++)
                    ldsm4(b4[nf], sB + boff + (uint32_t)(nf * (16 * PITCHB) + ks * 32));
                #pragma unroll
                for (int nf = 0; nf < 2; nf++)
                    #pragma unroll
                    for (int n8 = 0; n8 < 2; n8++)
                        mma16816h(acc[nf * 2 + n8], a4, b4[nf] + n8 * 2);
            }
            if (t == 31) {
                int row = wq * 16 + (lane >> 2);
                float inv0 = 1.0f / rowsum[row];
                float inv1 = 1.0f / rowsum[row + 8];
                #pragma unroll
                for (int f = 0; f < 4; f++) {
                    int col = dc * 128 + nh * 32 + f * 8 + (lane & 3) * 2;
                    float* o0 = out + ((size_t)b * SQn + qt * 128 + row) * Dh + col;
                    *(float2*)o0 = make_float2(acc[f][0] * inv0, acc[f][1] * inv0);
                    *(float2*)(o0 + 8 * Dh) = make_float2(acc[f][2] * inv1, acc[f][3] * inv1);
                }
            }
        }
    }
}

extern "C" void kernel_launch(void* const* d_in, const int* in_sizes, int n_in,
                              void* d_out, int out_size) {
    (void)in_sizes; (void)n_in; (void)out_size;
    const float* q = (const float*)d_in[0];
    const float* k = (const float*)d_in[1];
    const float* v = (const float*)d_in[2];
    float* out = (float*)d_out;

    cudaFuncSetAttribute(attn_main, cudaFuncAttributeMaxDynamicSharedMemorySize, SMEM_BYTES);

    dim3 pgrid(SKn / 32, Dh / 32, Bn);
    prep_all<<<pgrid, 256>>>(q, k, v);
    dim3 grid(NQT, Bn);
    attn_main<<<grid, THREADS, SMEM_BYTES>>>(out);
}